// round 17
// baseline (speedup 1.0000x reference)
#include <cuda_runtime.h>
#include <cuda_fp16.h>
#include <cstdint>

#define H 8192
#define T 64
#define NBLK 148           // persistent blocks: 1/SM (residency guaranteed)
#define NTHR 512           // 16 warps
#define RES_ROWS 14        // W_hh rows held in SMEM per block (14*16KB = 224KB)
#define RES_TOTAL (NBLK * RES_ROWS)          // 2072 rows SMEM-resident
#define STREAM_ROWS (H - RES_TOTAL)          // 6120 rows streamed
#define NCHUNK (STREAM_ROWS / 8)             // 765 chunks of 8 rows
#define SW_BYTES (RES_ROWS * H * 2)          // 229376 B dynamic smem

// Scratch (device globals: sanctioned allocation-free workaround).
__device__ __half g_whh[(size_t)H * (size_t)H];   // fp16 W_hh, 128 MiB
__device__ float g_pre[T * H];                    // pre[t][j] = x_t . W_ih^T

// ---- grid barrier state (sense-reversing) ----
__device__ unsigned g_cnt = 0;
__device__ volatile unsigned g_gen = 0;

__device__ __forceinline__ void grid_barrier() {
    __syncthreads();
    if (threadIdx.x == 0) {
        unsigned gen = g_gen;
        __threadfence();
        if (atomicAdd(&g_cnt, 1u) == NBLK - 1u) {
            atomicExch(&g_cnt, 0u);
            __threadfence();
            g_gen = gen + 1u;
        } else {
            while (g_gen == gen) __nanosleep(32);
        }
    }
    __syncthreads();
}

// ---------------------------------------------------------------------------
// tf32 mma helpers
// ---------------------------------------------------------------------------
__device__ __forceinline__ uint32_t f2tf(float f) {
    uint32_t u;
    asm("cvt.rna.tf32.f32 %0, %1;" : "=r"(u) : "f"(f));
    return u;
}
__device__ __forceinline__ void mma_tf32(float* c,
                                         uint32_t a0, uint32_t a1, uint32_t a2, uint32_t a3,
                                         uint32_t b0, uint32_t b1) {
    asm volatile("mma.sync.aligned.m16n8k8.row.col.f32.tf32.tf32.f32 "
                 "{%0,%1,%2,%3}, {%4,%5,%6,%7}, {%8,%9}, {%0,%1,%2,%3};"
                 : "+f"(c[0]), "+f"(c[1]), "+f"(c[2]), "+f"(c[3])
                 : "r"(a0), "r"(a1), "r"(a2), "r"(a3), "r"(b0), "r"(b1));
}

// ---------------------------------------------------------------------------
// K_PREP: fused (a) phase-1 tf32 GEMM -> g_pre, (b) W_hh fp32->fp16 convert.
// Streamed rows (>= RES_TOTAL) stored evict_last (their 100MB working set now
// fits in L2, so retention across steps is possible); resident rows stored
// evict_first (they will live in SMEM; keep them out of L2).
// ---------------------------------------------------------------------------
#define PREP_GEMM_BLOCKS (H / 64)                       // 128
#define PREP_CONV_BLOCKS ((size_t)H * H / 16 / 256)     // 16384

__global__ void __launch_bounds__(256) k_prep(const float* __restrict__ x,
                                              const float* __restrict__ wih,
                                              const float* __restrict__ whh) {
    if (blockIdx.x >= PREP_GEMM_BLOCKS) {
        size_t i = (((size_t)blockIdx.x - PREP_GEMM_BLOCKS) * 256u + threadIdx.x) * 16u;
        uint32_t o[8];
#pragma unroll
        for (int q = 0; q < 4; ++q) {
            float4 a = *reinterpret_cast<const float4*>(whh + i + q * 4);
            __half2 lo = __floats2half2_rn(a.x, a.y);
            __half2 hi = __floats2half2_rn(a.z, a.w);
            o[q * 2 + 0] = reinterpret_cast<unsigned int&>(lo);
            o[q * 2 + 1] = reinterpret_cast<unsigned int&>(hi);
        }
        if ((i >> 13) < RES_TOTAL) {   // row = i / H : SMEM-resident rows
            asm volatile("st.global.L2::evict_first.v8.b32 [%0], {%1,%2,%3,%4,%5,%6,%7,%8};"
                         :: "l"(g_whh + i),
                            "r"(o[0]), "r"(o[1]), "r"(o[2]), "r"(o[3]),
                            "r"(o[4]), "r"(o[5]), "r"(o[6]), "r"(o[7]) : "memory");
        } else {
            asm volatile("st.global.L2::evict_last.v8.b32 [%0], {%1,%2,%3,%4,%5,%6,%7,%8};"
                         :: "l"(g_whh + i),
                            "r"(o[0]), "r"(o[1]), "r"(o[2]), "r"(o[3]),
                            "r"(o[4]), "r"(o[5]), "r"(o[6]), "r"(o[7]) : "memory");
        }
        return;
    }

    // ---- phase-1 GEMM part (unchanged) ----
    __shared__ float As[64 * 36];
    __shared__ float Bs[64 * 36];

    const int tid = threadIdx.x;
    const int warp = tid >> 5;
    const int lane = tid & 31;
    const int wm = warp >> 2;
    const int wn = warp & 3;
    const int g = lane >> 2;
    const int tig = lane & 3;
    const int jb = blockIdx.x * 64;

    float acc[2][2][4];
#pragma unroll
    for (int mt = 0; mt < 2; ++mt)
#pragma unroll
        for (int nt = 0; nt < 2; ++nt)
#pragma unroll
            for (int i = 0; i < 4; ++i) acc[mt][nt][i] = 0.f;

    for (int kc = 0; kc < H; kc += 32) {
#pragma unroll
        for (int p = 0; p < 2; ++p) {
            int idx = tid + p * 256;
            int r = idx >> 3;
            int c4 = (idx & 7) * 4;
            float4 v = *reinterpret_cast<const float4*>(x + (size_t)r * H + kc + c4);
            *reinterpret_cast<float4*>(As + r * 36 + c4) = v;
            float4 w = *reinterpret_cast<const float4*>(wih + (size_t)(jb + r) * H + kc + c4);
            *reinterpret_cast<float4*>(Bs + r * 36 + c4) = w;
        }
        __syncthreads();

#pragma unroll
        for (int ks = 0; ks < 4; ++ks) {
            const int k0 = ks * 8;
            uint32_t a[2][4];
#pragma unroll
            for (int mt = 0; mt < 2; ++mt) {
                int mr = wm * 32 + mt * 16;
                a[mt][0] = f2tf(As[(mr + g)     * 36 + k0 + tig]);
                a[mt][1] = f2tf(As[(mr + g + 8) * 36 + k0 + tig]);
                a[mt][2] = f2tf(As[(mr + g)     * 36 + k0 + tig + 4]);
                a[mt][3] = f2tf(As[(mr + g + 8) * 36 + k0 + tig + 4]);
            }
            uint32_t bfr[2][2];
#pragma unroll
            for (int nt = 0; nt < 2; ++nt) {
                int nr = wn * 16 + nt * 8;
                bfr[nt][0] = f2tf(Bs[(nr + g) * 36 + k0 + tig]);
                bfr[nt][1] = f2tf(Bs[(nr + g) * 36 + k0 + tig + 4]);
            }
#pragma unroll
            for (int mt = 0; mt < 2; ++mt)
#pragma unroll
                for (int nt = 0; nt < 2; ++nt)
                    mma_tf32(acc[mt][nt], a[mt][0], a[mt][1], a[mt][2], a[mt][3],
                             bfr[nt][0], bfr[nt][1]);
        }
        __syncthreads();
    }

#pragma unroll
    for (int mt = 0; mt < 2; ++mt) {
        int t0 = wm * 32 + mt * 16 + g;
#pragma unroll
        for (int nt = 0; nt < 2; ++nt) {
            int j0 = jb + wn * 16 + nt * 8 + tig * 2;
            *reinterpret_cast<float2*>(g_pre + (size_t)t0 * H + j0) =
                make_float2(acc[mt][nt][0], acc[mt][nt][1]);
            *reinterpret_cast<float2*>(g_pre + (size_t)(t0 + 8) * H + j0) =
                make_float2(acc[mt][nt][2], acc[mt][nt][3]);
        }
    }
}

// ---------------------------------------------------------------------------
// FMA body shared by resident and streamed paths: 8 packed half2 regs x hr[16]
// ---------------------------------------------------------------------------
#define FMA16(S, W0, W1, W2, W3, W4, W5, W6, W7)                        \
    do {                                                                \
        float2 f0 = __half22float2(reinterpret_cast<__half2&>(W0));     \
        float2 f1 = __half22float2(reinterpret_cast<__half2&>(W1));     \
        float2 f2 = __half22float2(reinterpret_cast<__half2&>(W2));     \
        float2 f3 = __half22float2(reinterpret_cast<__half2&>(W3));     \
        float2 f4 = __half22float2(reinterpret_cast<__half2&>(W4));     \
        float2 f5 = __half22float2(reinterpret_cast<__half2&>(W5));     \
        float2 f6 = __half22float2(reinterpret_cast<__half2&>(W6));     \
        float2 f7 = __half22float2(reinterpret_cast<__half2&>(W7));     \
        float acc = S;                                                  \
        acc = fmaf(f0.x, hr[0],  acc);                                  \
        acc = fmaf(f0.y, hr[1],  acc);                                  \
        acc = fmaf(f1.x, hr[2],  acc);                                  \
        acc = fmaf(f1.y, hr[3],  acc);                                  \
        acc = fmaf(f2.x, hr[4],  acc);                                  \
        acc = fmaf(f2.y, hr[5],  acc);                                  \
        acc = fmaf(f3.x, hr[6],  acc);                                  \
        acc = fmaf(f3.y, hr[7],  acc);                                  \
        acc = fmaf(f4.x, hr[8],  acc);                                  \
        acc = fmaf(f4.y, hr[9],  acc);                                  \
        acc = fmaf(f5.x, hr[10], acc);                                  \
        acc = fmaf(f5.y, hr[11], acc);                                  \
        acc = fmaf(f6.x, hr[12], acc);                                  \
        acc = fmaf(f6.y, hr[13], acc);                                  \
        acc = fmaf(f7.x, hr[14], acc);                                  \
        acc = fmaf(f7.y, hr[15], acc);                                  \
        S = acc;                                                        \
    } while (0)

// ---------------------------------------------------------------------------
// K_RNN: persistent recurrence with SMEM-resident weight partition.
// 148 blocks x 512 threads (16 warps).  Warp w owns k-slice [w*512,(w+1)*512);
// lane owns 16 consecutive halves.  Each block permanently holds RES_ROWS
// rows of W_hh in SMEM (loaded once); per step it computes those rows from
// SMEM plus ~5 chunks of 8 streamed rows from g_whh (LDG.256, evict_last).
// ---------------------------------------------------------------------------
extern __shared__ __half sw[];   // RES_ROWS * H halves

__global__ void __launch_bounds__(NTHR, 1) k_rnn(float* __restrict__ out,
                                                 const float* __restrict__ b) {
    __shared__ float part[16][16];   // [row][warp]
    const int tid = threadIdx.x;
    const int warp = tid >> 5;
    const int lane = tid & 31;
    const int k0 = warp * 512 + lane * 16;

    // One-time: load this block's resident rows g_whh[blk*14 .. +14) into SMEM.
    {
        const uint4* src = reinterpret_cast<const uint4*>(
            g_whh + (size_t)blockIdx.x * RES_ROWS * H);
        uint4* dst = reinterpret_cast<uint4*>(sw);
#pragma unroll
        for (int i = 0; i < RES_ROWS * H / 8 / NTHR; ++i)     // 28 iters
            dst[i * NTHR + tid] = src[i * NTHR + tid];
    }
    __syncthreads();

    // ---- step 0: h0 = tanh(pre0 + b) ----
    for (int j = blockIdx.x * NTHR + tid; j < H; j += NBLK * NTHR)
        out[j] = tanhf(g_pre[j] + b[j]);
    grid_barrier();

    for (int t = 1; t < T; ++t) {
        const float* hprev = out + (size_t)(t - 1) * H;
        float* hout = out + (size_t)t * H;

        // Preload lane's 16 h values (matches both LDS and LDG weight layout).
        float hr[16];
#pragma unroll
        for (int q = 0; q < 4; ++q) {
            float4 a = *reinterpret_cast<const float4*>(hprev + k0 + q * 4);
            hr[q * 4 + 0] = a.x;
            hr[q * 4 + 1] = a.y;
            hr[q * 4 + 2] = a.z;
            hr[q * 4 + 3] = a.w;
        }

        // ---- resident rows from SMEM ----
        {
            float s[RES_ROWS];
#pragma unroll
            for (int r = 0; r < RES_ROWS; ++r) s[r] = 0.f;
#pragma unroll
            for (int r = 0; r < RES_ROWS; ++r) {
                const __half* wrow = sw + r * H + k0;
                uint4 wa = *reinterpret_cast<const uint4*>(wrow);      // halves 0..7
                uint4 wb = *reinterpret_cast<const uint4*>(wrow + 8);  // halves 8..15
                FMA16(s[r], wa.x, wa.y, wa.z, wa.w, wb.x, wb.y, wb.z, wb.w);
            }
#pragma unroll
            for (int off = 16; off > 0; off >>= 1)
#pragma unroll
                for (int r = 0; r < RES_ROWS; ++r)
                    s[r] += __shfl_xor_sync(0xFFFFFFFFu, s[r], off);
            if (lane == 0) {
#pragma unroll
                for (int r = 0; r < RES_ROWS; ++r) part[r][warp] = s[r];
            }
            __syncthreads();
            if (tid < RES_ROWS) {
                float v = 0.f;
#pragma unroll
                for (int w = 0; w < 16; ++w) v += part[tid][w];
                const int j = blockIdx.x * RES_ROWS + tid;
                hout[j] = tanhf(v + g_pre[(size_t)t * H + j] + b[j]);
            }
            __syncthreads();
        }

        // ---- streamed rows from DRAM/L2 ----
        for (int chunk = blockIdx.x; chunk < NCHUNK; chunk += NBLK) {
            const int jbase = RES_TOTAL + chunk * 8;
            const __half* wbase = g_whh + (size_t)jbase * H + k0;

            float s[8];
#pragma unroll
            for (int r = 0; r < 8; ++r) s[r] = 0.f;
#pragma unroll
            for (int r = 0; r < 8; ++r) {
                uint32_t w0, w1, w2, w3, w4, w5, w6, w7;
                asm volatile("ld.global.nc.L2::evict_last.v8.b32 "
                             "{%0,%1,%2,%3,%4,%5,%6,%7}, [%8];"
                             : "=r"(w0), "=r"(w1), "=r"(w2), "=r"(w3),
                               "=r"(w4), "=r"(w5), "=r"(w6), "=r"(w7)
                             : "l"(wbase + (size_t)r * H));
                FMA16(s[r], w0, w1, w2, w3, w4, w5, w6, w7);
            }
#pragma unroll
            for (int off = 16; off > 0; off >>= 1)
#pragma unroll
                for (int r = 0; r < 8; ++r)
                    s[r] += __shfl_xor_sync(0xFFFFFFFFu, s[r], off);
            if (lane == 0) {
#pragma unroll
                for (int r = 0; r < 8; ++r) part[r][warp] = s[r];
            }
            __syncthreads();
            if (tid < 8) {
                float v = 0.f;
#pragma unroll
                for (int w = 0; w < 16; ++w) v += part[tid][w];
                const int j = jbase + tid;
                hout[j] = tanhf(v + g_pre[(size_t)t * H + j] + b[j]);
            }
            __syncthreads();
        }
        grid_barrier();
    }
}

// ---------------------------------------------------------------------------
extern "C" void kernel_launch(void* const* d_in, const int* in_sizes, int n_in,
                              void* d_out, int out_size) {
    const float* x   = (const float*)d_in[0];   // (64, 8192)
    const float* wih = (const float*)d_in[1];   // (8192, 8192)
    const float* whh = (const float*)d_in[2];   // (8192, 8192)
    const float* b   = (const float*)d_in[3];   // (8192,)
    float* out = (float*)d_out;                 // 64*8192

    cudaFuncSetAttribute(k_rnn, cudaFuncAttributeMaxDynamicSharedMemorySize,
                         SW_BYTES);

    k_prep<<<(unsigned)(PREP_GEMM_BLOCKS + PREP_CONV_BLOCKS), 256>>>(x, wih, whh);
    k_rnn<<<NBLK, NTHR, SW_BYTES>>>(out, b);
}